// round 14
// baseline (speedup 1.0000x reference)
#include <cuda_runtime.h>
#include <cuda_fp16.h>
#include <math.h>
#include <stdint.h>

// ---------------- problem constants ----------------
#define HDIM 2048
#define FDIM 4096
#define NTOK 8192

// ---------------- GEMM tiling ----------------
#define BM 128
#define BN 128
#define BK 64               // fp16 elements per k-chunk (128B per row)
#define GTHREADS 128        // 4 warps: 2 (M) x 2 (N), warp tile 64x64
#define NSTAGE 3

// ---------------- device scratch (static globals; no allocation) ----------------
__device__ int g_cnt[2];
__device__ int g_list[2][NTOK];
__device__ __align__(128) __half g_X16[2][NTOK][HDIM];
__device__ __align__(128) __half g_H16[2][NTOK][FDIM];
__device__ __align__(128) __half g_Wa16[2][FDIM][HDIM];
__device__ __align__(128) __half g_Wb16[2][HDIM][FDIM];

// ---------------- PTX helpers (plain sm_80+ features only) ----------------
__device__ __forceinline__ void cpa16(uint32_t dst, const void* src) {
    asm volatile("cp.async.cg.shared.global [%0], [%1], 16;" :: "r"(dst), "l"(src));
}
__device__ __forceinline__ void ldsm4(uint32_t* r, uint32_t addr) {
    asm volatile("ldmatrix.sync.aligned.m8n8.x4.shared.b16 {%0,%1,%2,%3}, [%4];"
                 : "=r"(r[0]), "=r"(r[1]), "=r"(r[2]), "=r"(r[3]) : "r"(addr));
}
__device__ __forceinline__ void mma16816(float* c, const uint32_t* a, const uint32_t* b) {
    asm volatile("mma.sync.aligned.m16n8k16.row.col.f32.f16.f16.f32 "
                 "{%0,%1,%2,%3}, {%4,%5,%6,%7}, {%8,%9}, {%0,%1,%2,%3};"
                 : "+f"(c[0]), "+f"(c[1]), "+f"(c[2]), "+f"(c[3])
                 : "r"(a[0]), "r"(a[1]), "r"(a[2]), "r"(a[3]), "r"(b[0]), "r"(b[1]));
}

// smem tile: rows of 64 fp16 = 128B = 8 x 16B chunks, chunk ^= (row & 7)
__device__ __forceinline__ uint32_t smem_off(int row, int ch /*16B chunk 0..7*/) {
    return (uint32_t)(row * 128 + (ch ^ (row & 7)) * 16);
}

// ---------------- kernel: zero counters ----------------
__global__ void zero_counts_kernel() {
    if (threadIdx.x < 2) g_cnt[threadIdx.x] = 0;
}

// ---------------- kernel: gate + compact + gather(fp16) ----------------
__global__ void gate_gather_kernel(const float* __restrict__ x,
                                   const float* __restrict__ Wg) {
    __shared__ float wg[2 * HDIM];
    for (int i = threadIdx.x; i < 2 * HDIM; i += blockDim.x) wg[i] = Wg[i];
    __syncthreads();

    const int warp = threadIdx.x >> 5;
    const int lane = threadIdx.x & 31;
    const int token = blockIdx.x * 8 + warp;
    const float* xr = x + (size_t)token * HDIM;

    float s0 = 0.f, s1 = 0.f;
    for (int i = lane; i < HDIM; i += 32) {
        float v = xr[i];
        s0 += v * wg[i];
        s1 += v * wg[HDIM + i];
    }
    #pragma unroll
    for (int o = 16; o > 0; o >>= 1) {
        s0 += __shfl_xor_sync(0xffffffffu, s0, o);
        s1 += __shfl_xor_sync(0xffffffffu, s1, o);
    }
    const int e = (s1 > s0) ? 1 : 0;   // argmax(softmax)==argmax(logits); ties -> 0

    int pos = 0;
    if (lane == 0) pos = atomicAdd(&g_cnt[e], 1);
    pos = __shfl_sync(0xffffffffu, pos, 0);
    if (lane == 0) g_list[e][pos] = token;

    for (int i = lane * 4; i < HDIM; i += 128) {
        float4 v = *reinterpret_cast<const float4*>(xr + i);
        __half h4[4] = {__float2half(v.x), __float2half(v.y),
                        __float2half(v.z), __float2half(v.w)};
        *reinterpret_cast<uint2*>(&g_X16[e][pos][i]) = *reinterpret_cast<uint2*>(h4);
    }
}

// ---------------- kernel: all weights fp32 -> fp16 (one launch) ----------------
__global__ void wconv_all_kernel(const float* __restrict__ W0a, const float* __restrict__ W1a,
                                 const float* __restrict__ W0b, const float* __restrict__ W1b) {
    const int which = blockIdx.y;
    const float* src;
    __half* dst;
    switch (which) {
        case 0: src = W0a; dst = &g_Wa16[0][0][0]; break;
        case 1: src = W1a; dst = &g_Wa16[1][0][0]; break;
        case 2: src = W0b; dst = &g_Wb16[0][0][0]; break;
        default: src = W1b; dst = &g_Wb16[1][0][0]; break;
    }
    const size_t i = ((size_t)blockIdx.x * 256 + threadIdx.x) * 4;
    float4 v = *reinterpret_cast<const float4*>(src + i);
    __half h4[4] = {__float2half(v.x), __float2half(v.y),
                    __float2half(v.z), __float2half(v.w)};
    *reinterpret_cast<uint2*>(dst + i) = *reinterpret_cast<uint2*>(h4);
}

// ---------------- kernel: fp16 mma.sync GEMM, 128x128 CTA, 4 warps, 64x64 warp tile
// C[m,n] = sum_k A[m,k]*B[n,k], fp32 accum.  blockIdx.z = expert.
// Schedule: cp.async fill for stage t+2 is issued in two halves AFTER ks0/ks1
// MMAs are underway, keeping the post-barrier ldsm burst off the write burst.
template <int K, bool DOWN>
__global__ void __launch_bounds__(GTHREADS, 2)
moe_gemm(const float* __restrict__ bias0, const float* __restrict__ bias1,
         float* __restrict__ out) {
    const int e = blockIdx.z;
    const int cnt = g_cnt[e];
    const int m0 = blockIdx.y * BM;
    if (m0 >= cnt) return;
    const int n0 = blockIdx.x * BN;
    const float* bias = e ? bias1 : bias0;

    extern __shared__ char smem[];
    const uint32_t sb = (uint32_t)__cvta_generic_to_shared(smem);

    const int tid = threadIdx.x;
    const int lane = tid & 31;
    const int warp = tid >> 5;         // 0..3
    const int wm = warp >> 1;          // 0..1  (64 rows)
    const int wn = warp & 1;           // 0..1  (64 cols)
    const int g = lane >> 3;           // ldmatrix lane group

    const __half* A = DOWN ? &g_H16[e][0][0] : &g_X16[e][0][0];
    const __half* B = DOWN ? &g_Wb16[e][0][0] : &g_Wa16[e][0][0];

    // per stage: A 16KB (128 rows) | B 16KB (128 rows) = 32KB; 3 stages = 96KB
    constexpr uint32_t BUFB = 32768u;
    constexpr uint32_t BREG = 16384u;

    // half = 0: A tile chunks; half = 1: B tile chunks (8 cpa16 per thread each)
    auto fill_half = [&](int buf, int k0, int half) {
        const uint32_t bb = sb + buf * BUFB;
        #pragma unroll
        for (int i = 0; i < 8; i++) {
            int idx = tid + i * 128;            // 0..1023 16B chunks
            int c = idx & 7;
            int row = idx >> 3;
            if (half == 0) {
                cpa16(bb + smem_off(row, c),
                      A + (size_t)(m0 + row) * K + k0 + c * 8);
            } else {
                cpa16(bb + BREG + smem_off(row, c),
                      B + (size_t)(n0 + row) * K + k0 + c * 8);
            }
        }
    };
    auto commit = [&]() {
        asm volatile("cp.async.commit_group;" ::: "memory");
    };

    float acc[4][8][4];
    #pragma unroll
    for (int i = 0; i < 4; i++)
        #pragma unroll
        for (int j = 0; j < 8; j++)
            #pragma unroll
            for (int q = 0; q < 4; q++) acc[i][j][q] = 0.f;

    const int NT = K / BK;
    fill_half(0, 0, 0); fill_half(0, 0, 1); commit();
    fill_half(1, BK, 0); fill_half(1, BK, 1); commit();

    for (int t = 0; t < NT; t++) {
        const int buf = t % NSTAGE;
        if (t + 1 < NT) {
            asm volatile("cp.async.wait_group 1;" ::: "memory");
        } else {
            asm volatile("cp.async.wait_group 0;" ::: "memory");
        }
        __syncthreads();   // stage t visible; frees buffer (t-1)%3

        const int pf = (t + 2 < NT);
        const int pbuf = (t + 2) % NSTAGE;
        const int pk0 = (t + 2) * BK;

        const uint32_t bb = sb + buf * BUFB;
        #pragma unroll
        for (int ks = 0; ks < 4; ks++) {
            uint32_t af[4][4], bf[4][4];
            // interleave A/B ldsm so mma(af0,bf0) is eligible early
            #pragma unroll
            for (int tt = 0; tt < 4; tt++) {
                int arow = wm * 64 + tt * 16 + (g & 1) * 8 + (lane & 7);
                ldsm4(af[tt], bb + smem_off(arow, 2 * ks + (g >> 1)));
                int brow = wn * 64 + tt * 16 + (g >> 1) * 8 + (lane & 7);
                ldsm4(bf[tt], bb + BREG + smem_off(brow, 2 * ks + (g & 1)));
            }
            #pragma unroll
            for (int tm = 0; tm < 4; tm++)
                #pragma unroll
                for (int tn = 0; tn < 8; tn++)
                    mma16816(acc[tm][tn], af[tm], &bf[tn >> 1][(tn & 1) * 2]);

            // de-phased prefetch: stage t+2, A-half after ks0, B-half after ks1
            if (ks == 0 && pf) fill_half(pbuf, pk0, 0);
            if (ks == 1 && pf) { fill_half(pbuf, pk0, 1); commit(); }
        }
        if (!pf && t + 2 == NT) commit();   // keep group count consistent on tail
    }

    // ---------------- epilogue: bias + activation ----------------
    const bool gelu = (!DOWN) && (e == 0);
    const bool relu = (!DOWN) && (e == 1);
    #pragma unroll
    for (int tm = 0; tm < 4; tm++) {
        #pragma unroll
        for (int half = 0; half < 2; half++) {       // c0c1 (row) / c2c3 (row+8)
            const int m = m0 + wm * 64 + tm * 16 + half * 8 + (lane >> 2);
            if (m >= cnt) continue;
            float* orow = nullptr;
            __half* hrow = nullptr;
            if (DOWN) {
                orow = out + (size_t)g_list[e][m] * HDIM;
            } else {
                hrow = &g_H16[e][m][0];
            }
            #pragma unroll
            for (int tn = 0; tn < 8; tn++) {
                const int col = n0 + wn * 64 + tn * 8 + (lane & 3) * 2;
                #pragma unroll
                for (int q = 0; q < 2; q++) {
                    float v = acc[tm][tn][half * 2 + q] + bias[col + q];
                    if (gelu)
                        v = 0.5f * v * (1.0f + erff(v * 0.70710678118654752f));
                    else if (relu)
                        v = fmaxf(v, 0.0f);
                    if (DOWN) orow[col + q] = v;
                    else      hrow[col + q] = __float2half(v);
                }
            }
        }
    }
}

// ---------------- launch ----------------
extern "C" void kernel_launch(void* const* d_in, const int* in_sizes, int n_in,
                              void* d_out, int out_size) {
    const float* x   = (const float*)d_in[0];
    const float* Wg  = (const float*)d_in[1];
    const float* W0a = (const float*)d_in[2];
    const float* b0a = (const float*)d_in[3];
    const float* W0b = (const float*)d_in[4];
    const float* b0b = (const float*)d_in[5];
    const float* W1a = (const float*)d_in[6];
    const float* b1a = (const float*)d_in[7];
    const float* W1b = (const float*)d_in[8];
    const float* b1b = (const float*)d_in[9];
    float* out = (float*)d_out;

    constexpr int SMEM_SZ = NSTAGE * 32768;   // 96KB
    cudaFuncSetAttribute(moe_gemm<HDIM, false>,
                         cudaFuncAttributeMaxDynamicSharedMemorySize, SMEM_SZ);
    cudaFuncSetAttribute(moe_gemm<FDIM, true>,
                         cudaFuncAttributeMaxDynamicSharedMemorySize, SMEM_SZ);

    zero_counts_kernel<<<1, 32>>>();
    gate_gather_kernel<<<NTOK / 8, 256>>>(x, Wg);

    dim3 gW((FDIM * HDIM / 4) / 256, 4);
    wconv_all_kernel<<<gW, 256>>>(W0a, W1a, W0b, W1b);

    dim3 gUp(FDIM / BN, NTOK / BM, 2);   // (32, 64, 2)
    dim3 gDn(HDIM / BN, NTOK / BM, 2);   // (16, 64, 2)
    moe_gemm<HDIM, false><<<gUp, GTHREADS, SMEM_SZ>>>(b0a, b1a, nullptr);
    moe_gemm<FDIM, true><<<gDn, GTHREADS, SMEM_SZ>>>(b0b, b1b, out);
}

// round 15
// speedup vs baseline: 1.0160x; 1.0160x over previous
#include <cuda_runtime.h>
#include <cuda_fp16.h>
#include <math.h>
#include <stdint.h>

// ---------------- problem constants ----------------
#define HDIM 2048
#define FDIM 4096
#define NTOK 8192

// ---------------- GEMM tiling ----------------
#define BM 128
#define BN 128
#define BK 64               // fp16 elements per k-chunk (128B per row)
#define GTHREADS 128        // 4 warps: 2 (M) x 2 (N), warp tile 64x64
#define NSTAGE 3

// ---------------- device scratch (static globals; no allocation) ----------------
__device__ int g_cnt[2];
__device__ int g_done[2][NTOK / BM];   // up-phase completion counters per (e, m-block)
__device__ int g_list[2][NTOK];
__device__ __align__(128) __half g_X16[2][NTOK][HDIM];
__device__ __align__(128) __half g_H16[2][NTOK][FDIM];
__device__ __align__(128) __half g_Wa16[2][FDIM][HDIM];
__device__ __align__(128) __half g_Wb16[2][HDIM][FDIM];

// ---------------- PTX helpers (plain sm_80+ features only) ----------------
__device__ __forceinline__ void cpa16(uint32_t dst, const void* src) {
    asm volatile("cp.async.cg.shared.global [%0], [%1], 16;" :: "r"(dst), "l"(src));
}
__device__ __forceinline__ void ldsm4(uint32_t* r, uint32_t addr) {
    asm volatile("ldmatrix.sync.aligned.m8n8.x4.shared.b16 {%0,%1,%2,%3}, [%4];"
                 : "=r"(r[0]), "=r"(r[1]), "=r"(r[2]), "=r"(r[3]) : "r"(addr));
}
__device__ __forceinline__ void mma16816(float* c, const uint32_t* a, const uint32_t* b) {
    asm volatile("mma.sync.aligned.m16n8k16.row.col.f32.f16.f16.f32 "
                 "{%0,%1,%2,%3}, {%4,%5,%6,%7}, {%8,%9}, {%0,%1,%2,%3};"
                 : "+f"(c[0]), "+f"(c[1]), "+f"(c[2]), "+f"(c[3])
                 : "r"(a[0]), "r"(a[1]), "r"(a[2]), "r"(a[3]), "r"(b[0]), "r"(b[1]));
}

// smem tile: rows of 64 fp16 = 128B = 8 x 16B chunks, chunk ^= (row & 7)
__device__ __forceinline__ uint32_t smem_off(int row, int ch /*16B chunk 0..7*/) {
    return (uint32_t)(row * 128 + (ch ^ (row & 7)) * 16);
}

// ---------------- kernel: zero counters ----------------
__global__ void zero_counts_kernel() {
    if (threadIdx.x < 2) g_cnt[threadIdx.x] = 0;
    if (threadIdx.x < 2 * (NTOK / BM))
        (&g_done[0][0])[threadIdx.x] = 0;
}

// ---------------- kernel: gate + compact + gather(fp16) ----------------
__global__ void gate_gather_kernel(const float* __restrict__ x,
                                   const float* __restrict__ Wg) {
    __shared__ float wg[2 * HDIM];
    for (int i = threadIdx.x; i < 2 * HDIM; i += blockDim.x) wg[i] = Wg[i];
    __syncthreads();

    const int warp = threadIdx.x >> 5;
    const int lane = threadIdx.x & 31;
    const int token = blockIdx.x * 8 + warp;
    const float* xr = x + (size_t)token * HDIM;

    float s0 = 0.f, s1 = 0.f;
    for (int i = lane; i < HDIM; i += 32) {
        float v = xr[i];
        s0 += v * wg[i];
        s1 += v * wg[HDIM + i];
    }
    #pragma unroll
    for (int o = 16; o > 0; o >>= 1) {
        s0 += __shfl_xor_sync(0xffffffffu, s0, o);
        s1 += __shfl_xor_sync(0xffffffffu, s1, o);
    }
    const int e = (s1 > s0) ? 1 : 0;   // argmax(softmax)==argmax(logits); ties -> 0

    int pos = 0;
    if (lane == 0) pos = atomicAdd(&g_cnt[e], 1);
    pos = __shfl_sync(0xffffffffu, pos, 0);
    if (lane == 0) g_list[e][pos] = token;

    for (int i = lane * 4; i < HDIM; i += 128) {
        float4 v = *reinterpret_cast<const float4*>(xr + i);
        __half h4[4] = {__float2half(v.x), __float2half(v.y),
                        __float2half(v.z), __float2half(v.w)};
        *reinterpret_cast<uint2*>(&g_X16[e][pos][i]) = *reinterpret_cast<uint2*>(h4);
    }
}

// ---------------- kernel: all weights fp32 -> fp16 (one launch) ----------------
__global__ void wconv_all_kernel(const float* __restrict__ W0a, const float* __restrict__ W1a,
                                 const float* __restrict__ W0b, const float* __restrict__ W1b) {
    const int which = blockIdx.y;
    const float* src;
    __half* dst;
    switch (which) {
        case 0: src = W0a; dst = &g_Wa16[0][0][0]; break;
        case 1: src = W1a; dst = &g_Wa16[1][0][0]; break;
        case 2: src = W0b; dst = &g_Wb16[0][0][0]; break;
        default: src = W1b; dst = &g_Wb16[1][0][0]; break;
    }
    const size_t i = ((size_t)blockIdx.x * 256 + threadIdx.x) * 4;
    float4 v = *reinterpret_cast<const float4*>(src + i);
    __half h4[4] = {__float2half(v.x), __float2half(v.y),
                    __float2half(v.z), __float2half(v.w)};
    *reinterpret_cast<uint2*>(dst + i) = *reinterpret_cast<uint2*>(h4);
}

// ---------------- fused up+down GEMM -----------------------------------------
// grid = (32, 64, 4). z: 0/1 = up expert 0/1, 2/3 = down expert 0/1.
// z is the slowest-varying dispatch index, so ALL up blocks are dispatched
// before any down block; down blocks spin on g_done[e][mb] == FDIM/BN.
// Up:   C = X16 * Wa16^T  (K=HDIM), bias+act, store fp16 to H16, bump counter.
// Down: C = H16 * Wb16^T  (K=FDIM), bias, scatter fp32 rows to out.
__global__ void __launch_bounds__(GTHREADS, 2)
moe_fused(const float* __restrict__ b0a, const float* __restrict__ b1a,
          const float* __restrict__ b0b, const float* __restrict__ b1b,
          float* __restrict__ out) {
    const int z = blockIdx.z;
    const bool down = (z >= 2);
    const int e = z & 1;
    const int cnt = g_cnt[e];
    const int my = blockIdx.y;
    const int m0 = my * BM;
    if (m0 >= cnt) return;
    if (down && blockIdx.x >= HDIM / BN) return;   // down uses 16 n-blocks
    const int n0 = blockIdx.x * BN;

    const int K = down ? FDIM : HDIM;
    const float* bias = down ? (e ? b1b : b0b) : (e ? b1a : b0a);

    // down waits for its m-block's H rows to be complete (all up n-blocks)
    if (down) {
        if (threadIdx.x == 0) {
            volatile int* flag = &g_done[e][my];
            while (*flag < FDIM / BN) { __nanosleep(200); }
        }
        __syncthreads();
        __threadfence();   // acquire: order H reads after counter observation
    }

    extern __shared__ char smem[];
    const uint32_t sb = (uint32_t)__cvta_generic_to_shared(smem);

    const int tid = threadIdx.x;
    const int lane = tid & 31;
    const int warp = tid >> 5;         // 0..3
    const int wm = warp >> 1;          // 0..1  (64 rows)
    const int wn = warp & 1;           // 0..1  (64 cols)
    const int g = lane >> 3;           // ldmatrix lane group

    const __half* A = down ? &g_H16[e][0][0] : &g_X16[e][0][0];
    const __half* B = down ? &g_Wb16[e][0][0] : &g_Wa16[e][0][0];

    // per stage: A 16KB (128 rows) | B 16KB (128 rows) = 32KB; 3 stages = 96KB
    constexpr uint32_t BUFB = 32768u;
    constexpr uint32_t BREG = 16384u;

    auto fill = [&](int buf, int k0) {
        const uint32_t bb = sb + buf * BUFB;
        #pragma unroll
        for (int i = 0; i < 16; i++) {
            int idx = tid + i * 128;            // 0..2047 16B chunks
            int c = idx & 7;
            if (i < 8) {                        // A: 1024 chunks (128 rows)
                int row = idx >> 3;
                cpa16(bb + smem_off(row, c),
                      A + (size_t)(m0 + row) * K + k0 + c * 8);
            } else {                            // B: 1024 chunks (128 rows)
                int row = (idx - 1024) >> 3;
                cpa16(bb + BREG + smem_off(row, c),
                      B + (size_t)(n0 + row) * K + k0 + c * 8);
            }
        }
        asm volatile("cp.async.commit_group;" ::: "memory");
    };

    float acc[4][8][4];
    #pragma unroll
    for (int i = 0; i < 4; i++)
        #pragma unroll
        for (int j = 0; j < 8; j++)
            #pragma unroll
            for (int q = 0; q < 4; q++) acc[i][j][q] = 0.f;

    const int NT = K / BK;
    fill(0, 0);
    fill(1, BK);

    for (int t = 0; t < NT; t++) {
        const int buf = t % NSTAGE;
        if (t + 1 < NT) {
            asm volatile("cp.async.wait_group 1;" ::: "memory");
        } else {
            asm volatile("cp.async.wait_group 0;" ::: "memory");
        }
        __syncthreads();   // stage t visible; frees buffer (t-1)%3

        if (t + 2 < NT) fill((t + 2) % NSTAGE, (t + 2) * BK);

        const uint32_t bb = sb + buf * BUFB;
        #pragma unroll
        for (int ks = 0; ks < 4; ks++) {
            uint32_t af[4][4], bf[4][4];
            #pragma unroll
            for (int tm = 0; tm < 4; tm++) {   // A: 64 rows = 4 m16 tiles
                int row = wm * 64 + tm * 16 + (g & 1) * 8 + (lane & 7);
                ldsm4(af[tm], bb + smem_off(row, 2 * ks + (g >> 1)));
            }
            #pragma unroll
            for (int tp = 0; tp < 4; tp++) {   // B: 64 cols = 4 x (two n8 tiles)
                int row = wn * 64 + tp * 16 + (g >> 1) * 8 + (lane & 7);
                ldsm4(bf[tp], bb + BREG + smem_off(row, 2 * ks + (g & 1)));
            }
            #pragma unroll
            for (int tm = 0; tm < 4; tm++)
                #pragma unroll
                for (int tn = 0; tn < 8; tn++)
                    mma16816(acc[tm][tn], af[tm], &bf[tn >> 1][(tn & 1) * 2]);
        }
    }

    // ---------------- epilogue ----------------
    const bool gelu = (!down) && (e == 0);
    const bool relu = (!down) && (e == 1);
    #pragma unroll
    for (int tm = 0; tm < 4; tm++) {
        #pragma unroll
        for (int half = 0; half < 2; half++) {       // c0c1 (row) / c2c3 (row+8)
            const int m = m0 + wm * 64 + tm * 16 + half * 8 + (lane >> 2);
            if (m >= cnt) continue;
            float* orow = nullptr;
            __half* hrow = nullptr;
            if (down) {
                orow = out + (size_t)g_list[e][m] * HDIM;
            } else {
                hrow = &g_H16[e][m][0];
            }
            #pragma unroll
            for (int tn = 0; tn < 8; tn++) {
                const int col = n0 + wn * 64 + tn * 8 + (lane & 3) * 2;
                #pragma unroll
                for (int q = 0; q < 2; q++) {
                    float v = acc[tm][tn][half * 2 + q] + bias[col + q];
                    if (gelu)
                        v = 0.5f * v * (1.0f + erff(v * 0.70710678118654752f));
                    else if (relu)
                        v = fmaxf(v, 0.0f);
                    if (down) orow[col + q] = v;
                    else      hrow[col + q] = __float2half(v);
                }
            }
        }
    }

    // up block: publish completion of this (e, m-block, n-block)
    if (!down) {
        __threadfence();
        __syncthreads();
        if (tid == 0) atomicAdd(&g_done[e][my], 1);
    }
}

// ---------------- launch ----------------
extern "C" void kernel_launch(void* const* d_in, const int* in_sizes, int n_in,
                              void* d_out, int out_size) {
    const float* x   = (const float*)d_in[0];
    const float* Wg  = (const float*)d_in[1];
    const float* W0a = (const float*)d_in[2];
    const float* b0a = (const float*)d_in[3];
    const float* W0b = (const float*)d_in[4];
    const float* b0b = (const float*)d_in[5];
    const float* W1a = (const float*)d_in[6];
    const float* b1a = (const float*)d_in[7];
    const float* W1b = (const float*)d_in[8];
    const float* b1b = (const float*)d_in[9];
    float* out = (float*)d_out;

    constexpr int SMEM_SZ = NSTAGE * 32768;   // 96KB
    cudaFuncSetAttribute(moe_fused,
                         cudaFuncAttributeMaxDynamicSharedMemorySize, SMEM_SZ);

    zero_counts_kernel<<<1, 256>>>();
    gate_gather_kernel<<<NTOK / 8, 256>>>(x, Wg);

    dim3 gW((FDIM * HDIM / 4) / 256, 4);
    wconv_all_kernel<<<gW, 256>>>(W0a, W1a, W0b, W1b);

    dim3 gF(FDIM / BN, NTOK / BM, 4);   // (32, 64, 4): z 0/1 up, 2/3 down
    moe_fused<<<gF, GTHREADS, SMEM_SZ>>>(b0a, b1a, b0b, b1b, out);
}

// round 16
// speedup vs baseline: 1.0304x; 1.0142x over previous
#include <cuda_runtime.h>
#include <cuda_fp16.h>
#include <math.h>
#include <stdint.h>

// ---------------- problem constants ----------------
#define HDIM 2048
#define FDIM 4096
#define NTOK 8192
#define WELS (2 * FDIM * HDIM)        // elements in one weight pair (2 matrices)
#define HALF_WELS (FDIM * HDIM)       // 8388608

// ---------------- GEMM tiling ----------------
#define BM 128
#define BN 128
#define BK 64               // fp16 elements per k-chunk (128B per row)
#define GTHREADS 128        // 4 warps: 2 (M) x 2 (N), warp tile 64x64
#define NSTAGE 3

// ---------------- device scratch (static globals; no allocation) ----------------
__device__ int g_cnt[2];
__device__ int g_done[2][NTOK / BM];   // up-phase completion counters per (e, m-block)
__device__ int g_wb;                   // Wb-conversion completion counter (target 4096)
__device__ int g_list[2][NTOK];
__device__ __align__(128) __half g_X16[2][NTOK][HDIM];
__device__ __align__(128) __half g_H16[2][NTOK][FDIM];
__device__ __align__(128) __half g_Wa16[2][FDIM][HDIM];
__device__ __align__(128) __half g_Wb16[2][HDIM][FDIM];

// ---------------- PTX helpers (plain sm_80+ features only) ----------------
__device__ __forceinline__ void cpa16(uint32_t dst, const void* src) {
    asm volatile("cp.async.cg.shared.global [%0], [%1], 16;" :: "r"(dst), "l"(src));
}
__device__ __forceinline__ void ldsm4(uint32_t* r, uint32_t addr) {
    asm volatile("ldmatrix.sync.aligned.m8n8.x4.shared.b16 {%0,%1,%2,%3}, [%4];"
                 : "=r"(r[0]), "=r"(r[1]), "=r"(r[2]), "=r"(r[3]) : "r"(addr));
}
__device__ __forceinline__ void mma16816(float* c, const uint32_t* a, const uint32_t* b) {
    asm volatile("mma.sync.aligned.m16n8k16.row.col.f32.f16.f16.f32 "
                 "{%0,%1,%2,%3}, {%4,%5,%6,%7}, {%8,%9}, {%0,%1,%2,%3};"
                 : "+f"(c[0]), "+f"(c[1]), "+f"(c[2]), "+f"(c[3])
                 : "r"(a[0]), "r"(a[1]), "r"(a[2]), "r"(a[3]), "r"(b[0]), "r"(b[1]));
}

// smem tile: rows of 64 fp16 = 128B = 8 x 16B chunks, chunk ^= (row & 7)
__device__ __forceinline__ uint32_t smem_off(int row, int ch /*16B chunk 0..7*/) {
    return (uint32_t)(row * 128 + (ch ^ (row & 7)) * 16);
}

__device__ __forceinline__ void cvt4(const float* src, __half* dst) {
    float4 v = *reinterpret_cast<const float4*>(src);
    __half h4[4] = {__float2half(v.x), __float2half(v.y),
                    __float2half(v.z), __float2half(v.w)};
    *reinterpret_cast<uint2*>(dst) = *reinterpret_cast<uint2*>(h4);
}

// ---------------- kernel: zero counters ----------------
__global__ void zero_counts_kernel() {
    if (threadIdx.x < 2) g_cnt[threadIdx.x] = 0;
    if (threadIdx.x < 2 * (NTOK / BM))
        (&g_done[0][0])[threadIdx.x] = 0;
    if (threadIdx.x == 200) g_wb = 0;
}

// ---------------- kernel: prep = gate+gather (blocks 0..1023) | Wa conv (1024..5119)
__global__ void prep_kernel(const float* __restrict__ x, const float* __restrict__ Wg,
                            const float* __restrict__ W0a, const float* __restrict__ W1a) {
    const int b = blockIdx.x;
    if (b < 1024) {
        // ---- gate role: 8 warps, one token each ----
        __shared__ float wg[2 * HDIM];
        for (int i = threadIdx.x; i < 2 * HDIM; i += blockDim.x) wg[i] = Wg[i];
        __syncthreads();

        const int warp = threadIdx.x >> 5;
        const int lane = threadIdx.x & 31;
        const int token = b * 8 + warp;
        const float* xr = x + (size_t)token * HDIM;

        float s0 = 0.f, s1 = 0.f;
        for (int i = lane; i < HDIM; i += 32) {
            float v = xr[i];
            s0 += v * wg[i];
            s1 += v * wg[HDIM + i];
        }
        #pragma unroll
        for (int o = 16; o > 0; o >>= 1) {
            s0 += __shfl_xor_sync(0xffffffffu, s0, o);
            s1 += __shfl_xor_sync(0xffffffffu, s1, o);
        }
        const int e = (s1 > s0) ? 1 : 0;   // argmax(softmax)==argmax(logits); ties -> 0

        int pos = 0;
        if (lane == 0) pos = atomicAdd(&g_cnt[e], 1);
        pos = __shfl_sync(0xffffffffu, pos, 0);
        if (lane == 0) g_list[e][pos] = token;

        for (int i = lane * 4; i < HDIM; i += 128) {
            float4 v = *reinterpret_cast<const float4*>(xr + i);
            __half h4[4] = {__float2half(v.x), __float2half(v.y),
                            __float2half(v.z), __float2half(v.w)};
            *reinterpret_cast<uint2*>(&g_X16[e][pos][i]) = *reinterpret_cast<uint2*>(h4);
        }
    } else {
        // ---- Wa conversion role: 4096 blocks x 4096 elements ----
        const int wid2 = b - 1024;                       // 0..4095
        const long base = (long)wid2 * 4096;
        const int e2 = (base >= HALF_WELS) ? 1 : 0;      // slice-aligned split
        const float* src = e2 ? W1a : W0a;
        __half* dst = e2 ? &g_Wa16[1][0][0] : &g_Wa16[0][0][0];
        const long off = base - (e2 ? (long)HALF_WELS : 0);
        #pragma unroll
        for (int it = 0; it < 4; it++) {
            long i = off + it * 1024 + threadIdx.x * 4;
            cvt4(src + i, dst + i);
        }
    }
}

// ---------------- fused up+down GEMM + in-kernel Wb conversion -----------------
// grid = (32, 64, 4). z: 0/1 = up expert 0/1, 2/3 = down expert 0/1.
// z is the slowest dispatch index: all up blocks dispatch before any down block.
// Every up block (alive or dead) converts a 4096-element Wb slice and bumps g_wb.
// Down blocks spin on g_done[e][my]==32 AND g_wb==4096.
__global__ void __launch_bounds__(GTHREADS, 2)
moe_fused(const float* __restrict__ b0a, const float* __restrict__ b1a,
          const float* __restrict__ b0b, const float* __restrict__ b1b,
          const float* __restrict__ W0b, const float* __restrict__ W1b,
          float* __restrict__ out) {
    const int z = blockIdx.z;
    const bool down = (z >= 2);
    const int e = z & 1;
    const int cnt = g_cnt[e];
    const int my = blockIdx.y;
    const int m0 = my * BM;
    const int tid = threadIdx.x;

    bool alive = (m0 < cnt);
    if (down && (blockIdx.x >= HDIM / BN || !alive)) return;

    if (down) {
        if (tid == 0) {
            volatile int* f = &g_done[e][my];
            while (*f < FDIM / BN) { __nanosleep(200); }
            volatile int* w = &g_wb;
            while (*w < 4096) { __nanosleep(200); }
        }
        __syncthreads();
        __threadfence();   // order H/Wb reads after counter observation
    }

    if (alive) {
        const int n0 = blockIdx.x * BN;
        const int K = down ? FDIM : HDIM;
        const float* bias = down ? (e ? b1b : b0b) : (e ? b1a : b0a);

        extern __shared__ char smem[];
        const uint32_t sb = (uint32_t)__cvta_generic_to_shared(smem);

        const int lane = tid & 31;
        const int warp = tid >> 5;         // 0..3
        const int wm = warp >> 1;          // 0..1  (64 rows)
        const int wn = warp & 1;           // 0..1  (64 cols)
        const int g = lane >> 3;           // ldmatrix lane group

        const __half* A = down ? &g_H16[e][0][0] : &g_X16[e][0][0];
        const __half* B = down ? &g_Wb16[e][0][0] : &g_Wa16[e][0][0];

        constexpr uint32_t BUFB = 32768u;
        constexpr uint32_t BREG = 16384u;

        auto fill = [&](int buf, int k0) {
            const uint32_t bb = sb + buf * BUFB;
            #pragma unroll
            for (int i = 0; i < 16; i++) {
                int idx = tid + i * 128;            // 0..2047 16B chunks
                int c = idx & 7;
                if (i < 8) {
                    int row = idx >> 3;
                    cpa16(bb + smem_off(row, c),
                          A + (size_t)(m0 + row) * K + k0 + c * 8);
                } else {
                    int row = (idx - 1024) >> 3;
                    cpa16(bb + BREG + smem_off(row, c),
                          B + (size_t)(n0 + row) * K + k0 + c * 8);
                }
            }
            asm volatile("cp.async.commit_group;" ::: "memory");
        };

        float acc[4][8][4];
        #pragma unroll
        for (int i = 0; i < 4; i++)
            #pragma unroll
            for (int j = 0; j < 8; j++)
                #pragma unroll
                for (int q = 0; q < 4; q++) acc[i][j][q] = 0.f;

        const int NT = K / BK;
        fill(0, 0);
        fill(1, BK);

        for (int t = 0; t < NT; t++) {
            const int buf = t % NSTAGE;
            if (t + 1 < NT) {
                asm volatile("cp.async.wait_group 1;" ::: "memory");
            } else {
                asm volatile("cp.async.wait_group 0;" ::: "memory");
            }
            __syncthreads();   // stage t visible; frees buffer (t-1)%3

            if (t + 2 < NT) fill((t + 2) % NSTAGE, (t + 2) * BK);

            const uint32_t bb = sb + buf * BUFB;
            #pragma unroll
            for (int ks = 0; ks < 4; ks++) {
                uint32_t af[4][4], bf[4][4];
                #pragma unroll
                for (int tm = 0; tm < 4; tm++) {
                    int row = wm * 64 + tm * 16 + (g & 1) * 8 + (lane & 7);
                    ldsm4(af[tm], bb + smem_off(row, 2 * ks + (g >> 1)));
                }
                #pragma unroll
                for (int tp = 0; tp < 4; tp++) {
                    int row = wn * 64 + tp * 16 + (g >> 1) * 8 + (lane & 7);
                    ldsm4(bf[tp], bb + BREG + smem_off(row, 2 * ks + (g & 1)));
                }
                #pragma unroll
                for (int tm = 0; tm < 4; tm++)
                    #pragma unroll
                    for (int tn = 0; tn < 8; tn++)
                        mma16816(acc[tm][tn], af[tm], &bf[tn >> 1][(tn & 1) * 2]);
            }
        }

        // epilogue
        const bool gelu = (!down) && (e == 0);
        const bool relu = (!down) && (e == 1);
        #pragma unroll
        for (int tm = 0; tm < 4; tm++) {
            #pragma unroll
            for (int half = 0; half < 2; half++) {
                const int m = m0 + wm * 64 + tm * 16 + half * 8 + (lane >> 2);
                if (m >= cnt) continue;
                float* orow = nullptr;
                __half* hrow = nullptr;
                if (down) {
                    orow = out + (size_t)g_list[e][m] * HDIM;
                } else {
                    hrow = &g_H16[e][m][0];
                }
                #pragma unroll
                for (int tn = 0; tn < 8; tn++) {
                    const int col = n0 + wn * 64 + tn * 8 + (lane & 3) * 2;
                    #pragma unroll
                    for (int q = 0; q < 2; q++) {
                        float v = acc[tm][tn][half * 2 + q] + bias[col + q];
                        if (gelu)
                            v = 0.5f * v * (1.0f + erff(v * 0.70710678118654752f));
                        else if (relu)
                            v = fmaxf(v, 0.0f);
                        if (down) orow[col + q] = v;
                        else      hrow[col + q] = __float2half(v);
                    }
                }
            }
        }
    }

    // ---- up blocks (alive or dead): convert a Wb slice, then publish ----
    if (!down) {
        const int upid = z * 2048 + my * 32 + blockIdx.x;   // 0..4095
        const long base = (long)upid * 4096;
        const int e2 = (base >= HALF_WELS) ? 1 : 0;
        const float* src = e2 ? W1b : W0b;
        __half* dst = e2 ? &g_Wb16[1][0][0] : &g_Wb16[0][0][0];
        const long off = base - (e2 ? (long)HALF_WELS : 0);
        #pragma unroll
        for (int it = 0; it < 8; it++) {
            long i = off + it * 512 + tid * 4;
            cvt4(src + i, dst + i);
        }
        __syncthreads();
        __threadfence();
        if (tid == 0) {
            if (alive) atomicAdd(&g_done[e][my], 1);
            atomicAdd(&g_wb, 1);
        }
    }
}

// ---------------- launch ----------------
extern "C" void kernel_launch(void* const* d_in, const int* in_sizes, int n_in,
                              void* d_out, int out_size) {
    const float* x   = (const float*)d_in[0];
    const float* Wg  = (const float*)d_in[1];
    const float* W0a = (const float*)d_in[2];
    const float* b0a = (const float*)d_in[3];
    const float* W0b = (const float*)d_in[4];
    const float* b0b = (const float*)d_in[5];
    const float* W1a = (const float*)d_in[6];
    const float* b1a = (const float*)d_in[7];
    const float* W1b = (const float*)d_in[8];
    const float* b1b = (const float*)d_in[9];
    float* out = (float*)d_out;

    constexpr int SMEM_SZ = NSTAGE * 32768;   // 96KB
    cudaFuncSetAttribute(moe_fused,
                         cudaFuncAttributeMaxDynamicSharedMemorySize, SMEM_SZ);

    zero_counts_kernel<<<1, 256>>>();
    prep_kernel<<<5120, 256>>>(x, Wg, W0a, W1a);

    dim3 gF(FDIM / BN, NTOK / BM, 4);   // (32, 64, 4): z 0/1 up, 2/3 down
    moe_fused<<<gF, GTHREADS, SMEM_SZ>>>(b0a, b1a, b0b, b1b, W0b, W1b, out);
}